// round 15
// baseline (speedup 1.0000x reference)
#include <cuda_runtime.h>

#define SEQ    1024
#define BATCH  64
#define UNITS  512
#define ORDER  128
#define INDIM  512

typedef unsigned long long ull;

// scratch (device globals: no allocation allowed)
__device__ float g_xe[BATCH * SEQ];
__device__ int   g_flag[16 * 8 * 32];     // [g][slice], 128B-strided monotonic flags
__device__ float g_M2[ORDER * UNITS];     // (I+AT) @ MK, fp64-accumulated
__device__ float g_bmk[UNITS];            // BT @ MK

// ---------------------------------------------------------------------------
// f32x2 helpers
// ---------------------------------------------------------------------------
__device__ __forceinline__ void ffma2(ull& d, ull a, ull b) {
    asm("fma.rn.f32x2 %0, %1, %2, %0;" : "+l"(d) : "l"(a), "l"(b));
}
__device__ __forceinline__ ull pack2(float lo, float hi) {
    ull r;
    asm("mov.b64 %0, {%1, %2};" : "=l"(r) : "f"(lo), "f"(hi));
    return r;
}
__device__ __forceinline__ float hsum2(ull v) {
    float lo, hi;
    asm("mov.b64 {%0, %1}, %2;" : "=f"(lo), "=f"(hi) : "l"(v));
    return lo + hi;
}

// ---------------------------------------------------------------------------
// Kernel 0: M2 = (I+AT)@MK, bmk = BT@MK (fp64 accumulation).
// ---------------------------------------------------------------------------
__global__ void __launch_bounds__(512) prep_kernel(const float* __restrict__ AT,
                                                   const float* __restrict__ BT,
                                                   const float* __restrict__ MK) {
    __shared__ float row[ORDER];
    const int i = blockIdx.x;
    const int j = threadIdx.x;
    if (i < ORDER) {
        if (j < ORDER) row[j] = AT[i * ORDER + j] + (j == i ? 1.f : 0.f);
        __syncthreads();
        double acc = 0.0;
#pragma unroll 8
        for (int k = 0; k < ORDER; k++)
            acc += (double)row[k] * (double)MK[k * UNITS + j];
        g_M2[i * UNITS + j] = (float)acc;
    } else {
        double acc = 0.0;
#pragma unroll 8
        for (int k = 0; k < ORDER; k++)
            acc += (double)BT[k] * (double)MK[k * UNITS + j];
        g_bmk[j] = (float)acc;
    }
}

// ---------------------------------------------------------------------------
// Kernel 1: xe = x @ input_encoders; reset the 128 slice flags.
// ---------------------------------------------------------------------------
__global__ void __launch_bounds__(256) xe_kernel(const float* __restrict__ x,
                                                 const float* __restrict__ ie) {
    if (blockIdx.x == 0 && threadIdx.x < 128) g_flag[threadIdx.x * 32] = 0;
    const int warp = threadIdx.x >> 5;
    const int lane = threadIdx.x & 31;
    const int row  = blockIdx.x * 8 + warp;
    const float* xr = x + (size_t)row * INDIM;
    float s = 0.f;
#pragma unroll
    for (int k = lane; k < INDIM; k += 32) s += xr[k] * ie[k];
#pragma unroll
    for (int o = 16; o > 0; o >>= 1) s += __shfl_down_sync(0xffffffffu, s, o);
    if (lane == 0) g_xe[row] = s;
}

// ---------------------------------------------------------------------------
// Kernel 2: prex = X @ input_kernel (FFMA2 GEMM, proven R5..R14), into d_out.
// ---------------------------------------------------------------------------
__global__ void __launch_bounds__(256, 2) gemm_kernel(const float* __restrict__ A,
                                                      const float* __restrict__ B,
                                                      float* __restrict__ C) {
    __shared__ float As[16][132];
    __shared__ float Bs[16][128];
    const int m0  = blockIdx.x * 128;
    const int n0  = blockIdx.y * 128;
    const int tid = threadIdx.x;
    const int tx  = tid & 15;
    const int ty  = tid >> 4;

    ull acc[8][4];
#pragma unroll
    for (int i = 0; i < 8; i++)
#pragma unroll
        for (int j = 0; j < 4; j++) acc[i][j] = 0ull;

    for (int k0 = 0; k0 < 512; k0 += 16) {
#pragma unroll
        for (int i = 0; i < 2; i++) {
            int idx = tid + i * 256;
            int row = idx >> 2;
            int c4  = (idx & 3) << 2;
            float4 v = *reinterpret_cast<const float4*>(&A[(size_t)(m0 + row) * 512 + k0 + c4]);
            As[c4 + 0][row] = v.x; As[c4 + 1][row] = v.y;
            As[c4 + 2][row] = v.z; As[c4 + 3][row] = v.w;
        }
#pragma unroll
        for (int i = 0; i < 2; i++) {
            int idx = tid + i * 256;
            int row = idx >> 5;
            int c4  = (idx & 31) << 2;
            *reinterpret_cast<float4*>(&Bs[row][c4]) =
                *reinterpret_cast<const float4*>(&B[(size_t)(k0 + row) * 512 + n0 + c4]);
        }
        __syncthreads();
#pragma unroll
        for (int k = 0; k < 16; k++) {
            ulonglong2 b01 = *reinterpret_cast<const ulonglong2*>(&Bs[k][tx * 8]);
            ulonglong2 b23 = *reinterpret_cast<const ulonglong2*>(&Bs[k][tx * 8 + 4]);
            float4 ra0 = *reinterpret_cast<const float4*>(&As[k][ty * 8]);
            float4 ra1 = *reinterpret_cast<const float4*>(&As[k][ty * 8 + 4]);
            float rm[8] = {ra0.x, ra0.y, ra0.z, ra0.w, ra1.x, ra1.y, ra1.z, ra1.w};
#pragma unroll
            for (int i = 0; i < 8; i++) {
                ull rp = pack2(rm[i], rm[i]);
                ffma2(acc[i][0], rp, b01.x);
                ffma2(acc[i][1], rp, b01.y);
                ffma2(acc[i][2], rp, b23.x);
                ffma2(acc[i][3], rp, b23.y);
            }
        }
        __syncthreads();
    }
#pragma unroll
    for (int i = 0; i < 8; i++) {
        size_t base = (size_t)(m0 + ty * 8 + i) * 512 + n0 + tx * 8;
        ulonglong2 o0; o0.x = acc[i][0]; o0.y = acc[i][1];
        ulonglong2 o1; o1.x = acc[i][2]; o1.y = acc[i][3];
        *reinterpret_cast<ulonglong2*>(&C[base])     = o0;
        *reinterpret_cast<ulonglong2*>(&C[base + 4]) = o1;
    }
}

// ---------------------------------------------------------------------------
// Kernel 3: recurrence, dataflow exchange, SINGLE-POLLER + nanosleep.
// CTA (sl,g): batches 4g..4g+3, units 64sl..64sl+63.
//   h_t = tanh(prex + h_{t-1}@HK + m_{t-1}@M2 + u_t*bmk)
//   m_t = m_{t-1}@(I+AT) + u_t*BT
// Warp-group j consumes producer-CTA j's h slice. ONE lane polls the flag
// (ld.acquire.gpu + __nanosleep backoff); the named barrier broadcasts the
// acquire to the group. Keeps the L1tex FIFO clear of redundant poll loads
// so producer STGs / release stores / data LDGs are not starved.
// ---------------------------------------------------------------------------
struct Smem {
    float HKs2[UNITS * 64];   // 131072 B: [(k>>2)*256 + u*4 + (k&3)]
    float M2s2[ORDER * 64];   //  32768 B: same packing
    float hbuf[4][512];       //   8192 B: slice j region owned by warp-group j
    float mbuf[4][128];       //   2048 B: m_{t-1}
    float predH[8][4][64];    //   8192 B: hk partials   [j][b][u]
    float predQ[4][8][64];    //   8192 B: m@M2 partials [b][ksh][uh]
    float predM[4][4][128];   //   8192 B: m@(I+AT)      [ks3][b][o3]
    float predU[8][2][4];     //    256 B: h·he partials [j][warp][b]
    float he[512];
    float me[128];
    float bt[128];
    float bmkl[64];
    float mme[4];
};

__global__ void __launch_bounds__(512, 1)
recur_kernel(const float* __restrict__ he, const float* __restrict__ me,
             const float* __restrict__ HK, const float* __restrict__ MK,
             const float* __restrict__ AT, const float* __restrict__ BT,
             float* __restrict__ out) {
    extern __shared__ __align__(16) unsigned char smem_raw[];
    Smem* s = reinterpret_cast<Smem*>(smem_raw);

    const int tid = threadIdx.x;
    const int sl  = blockIdx.x;      // produced slice 0..7
    const int g   = blockIdx.y;      // batch group 0..15
    const int us  = sl * 64;

    // ---- stationary weights ----
    for (int i = tid; i < UNITS * 64; i += 512) {
        int k = i >> 6, u = i & 63;
        s->HKs2[(k >> 2) * 256 + u * 4 + (k & 3)] = HK[k * 512 + us + u];
    }
    for (int i = tid; i < ORDER * 64; i += 512) {
        int k = i >> 6, u = i & 63;
        s->M2s2[(k >> 2) * 256 + u * 4 + (k & 3)] = g_M2[k * 512 + us + u];
    }
    s->he[tid] = he[tid];
    if (tid < 128) { s->me[tid] = me[tid]; s->bt[tid] = BT[tid]; }
    if (tid < 64)  s->bmkl[tid] = g_bmk[us + tid];
    if (tid < 128) (&s->mbuf[0][0])[tid * 4 + 0] = 0.f,
                   (&s->mbuf[0][0])[tid * 4 + 1] = 0.f,
                   (&s->mbuf[0][0])[tid * 4 + 2] = 0.f,
                   (&s->mbuf[0][0])[tid * 4 + 3] = 0.f;

    // (I+AT) in registers: thread (o3 = tid>>2, ks3 = tid&3)
    const int o3 = tid >> 2, ks3 = tid & 3, kb3 = ks3 * 32;
    ull am2[16];
#pragma unroll
    for (int j = 0; j < 16; j++) {
        int k = kb3 + 2 * j;
        float a0 = AT[k * 128 + o3]       + (k == o3       ? 1.f : 0.f);
        float a1 = AT[(k + 1) * 128 + o3] + ((k + 1) == o3 ? 1.f : 0.f);
        am2[j] = pack2(a0, a1);
    }
    __syncthreads();

    const int uh  = tid & 63, ksh = tid >> 6;     // slice-group layout
    const int jsl = ksh;                           // consumed slice id
    const int wip = (tid >> 5) & 1;                // warp within pair
    volatile int* myflag = &g_flag[(g * 8 + sl) * 32];
    const int* cflag = &g_flag[(g * 8 + jsl) * 32];

    for (int t = 0; t < SEQ; ++t) {
        // ======== phase A: purely local (m_{t-1}) ========
        float2 prex = make_float2(0.f, 0.f);
        float  xv = 0.f;
        if (tid < 128) {
            int b = tid >> 5, ui = tid & 31;
            prex = __ldg(reinterpret_cast<const float2*>(
                &out[(size_t)((4 * g + b) * SEQ + t) * UNITS + us + 2 * ui]));
            xv = __ldg(&g_xe[(4 * g + b) * SEQ + t]);
            // mme partial: m·me
            float pm = 0.f;
#pragma unroll
            for (int q = 0; q < 4; q++)
                pm += s->mbuf[b][ui + 32 * q] * s->me[ui + 32 * q];
#pragma unroll
            for (int o = 16; o > 0; o >>= 1)
                pm += __shfl_down_sync(0xffffffffu, pm, o);
            if (ui == 0) s->mme[b] = pm;
        }

        // mq partial: m_{t-1} @ M2 slice -> predQ[b][ksh][uh]
        {
            ull q0 = 0, q1 = 0, q2 = 0, q3 = 0;
            const int k0 = ksh * 16;
#pragma unroll
            for (int kk = 0; kk < 16; kk += 4) {
                const int k = k0 + kk;
                ulonglong2 w  = *reinterpret_cast<const ulonglong2*>(&s->M2s2[(k >> 2) * 256 + uh * 4]);
                ulonglong2 m0 = *reinterpret_cast<const ulonglong2*>(&s->mbuf[0][k]);
                ulonglong2 m1 = *reinterpret_cast<const ulonglong2*>(&s->mbuf[1][k]);
                ulonglong2 m2 = *reinterpret_cast<const ulonglong2*>(&s->mbuf[2][k]);
                ulonglong2 m3 = *reinterpret_cast<const ulonglong2*>(&s->mbuf[3][k]);
                ffma2(q0, m0.x, w.x); ffma2(q0, m0.y, w.y);
                ffma2(q1, m1.x, w.x); ffma2(q1, m1.y, w.y);
                ffma2(q2, m2.x, w.x); ffma2(q2, m2.y, w.y);
                ffma2(q3, m3.x, w.x); ffma2(q3, m3.y, w.y);
            }
            s->predQ[0][ksh][uh] = hsum2(q0);
            s->predQ[1][ksh][uh] = hsum2(q1);
            s->predQ[2][ksh][uh] = hsum2(q2);
            s->predQ[3][ksh][uh] = hsum2(q3);
        }

        // predM partial: m_{t-1} @ (I+AT) -> predM[ks3][b][o3]
        {
            ull c0 = 0, c1 = 0, c2 = 0, c3 = 0;
#pragma unroll
            for (int j = 0; j < 16; j += 2) {
                const int k = kb3 + 2 * j;
                ulonglong2 m0 = *reinterpret_cast<const ulonglong2*>(&s->mbuf[0][k]);
                ulonglong2 m1 = *reinterpret_cast<const ulonglong2*>(&s->mbuf[1][k]);
                ulonglong2 m2 = *reinterpret_cast<const ulonglong2*>(&s->mbuf[2][k]);
                ulonglong2 m3 = *reinterpret_cast<const ulonglong2*>(&s->mbuf[3][k]);
                ffma2(c0, m0.x, am2[j]); ffma2(c0, m0.y, am2[j + 1]);
                ffma2(c1, m1.x, am2[j]); ffma2(c1, m1.y, am2[j + 1]);
                ffma2(c2, m2.x, am2[j]); ffma2(c2, m2.y, am2[j + 1]);
                ffma2(c3, m3.x, am2[j]); ffma2(c3, m3.y, am2[j + 1]);
            }
            s->predM[ks3][0][o3] = hsum2(c0);
            s->predM[ks3][1][o3] = hsum2(c1);
            s->predM[ks3][2][o3] = hsum2(c2);
            s->predM[ks3][3][o3] = hsum2(c3);
        }

        // ======== phase B: per-slice consume (warp-group jsl) ========
        float hv0 = 0.f, hv1 = 0.f, hv2 = 0.f, hv3 = 0.f;
        if (t > 0) {
            // ONE lane polls; nanosleep keeps the LSU FIFO clear.
            if ((tid & 63) == 0) {
                int f;
                while (true) {
                    asm volatile("ld.acquire.gpu.global.s32 %0, [%1];"
                                 : "=r"(f) : "l"(cflag) : "memory");
                    if (f >= t) break;
                    __nanosleep(64);
                }
            }
            // named barrier broadcasts the acquire to the whole group
            asm volatile("bar.sync %0, 64;" :: "r"(2 + jsl) : "memory");
            const size_t tb = (size_t)(4 * g) * SEQ + (t - 1);
            hv0 = __ldcg(&out[(tb           ) * UNITS + jsl * 64 + uh]);
            hv1 = __ldcg(&out[(tb +     SEQ ) * UNITS + jsl * 64 + uh]);
            hv2 = __ldcg(&out[(tb + 2 * SEQ ) * UNITS + jsl * 64 + uh]);
            hv3 = __ldcg(&out[(tb + 3 * SEQ ) * UNITS + jsl * 64 + uh]);
        }
        s->hbuf[0][jsl * 64 + uh] = hv0;
        s->hbuf[1][jsl * 64 + uh] = hv1;
        s->hbuf[2][jsl * 64 + uh] = hv2;
        s->hbuf[3][jsl * 64 + uh] = hv3;

        // u-dot partial from own registers
        {
            const float hek = s->he[jsl * 64 + uh];
            float p0 = hv0 * hek, p1 = hv1 * hek, p2 = hv2 * hek, p3 = hv3 * hek;
#pragma unroll
            for (int o = 16; o > 0; o >>= 1) {
                p0 += __shfl_down_sync(0xffffffffu, p0, o);
                p1 += __shfl_down_sync(0xffffffffu, p1, o);
                p2 += __shfl_down_sync(0xffffffffu, p2, o);
                p3 += __shfl_down_sync(0xffffffffu, p3, o);
            }
            if ((tid & 31) == 0) {
                s->predU[jsl][wip][0] = p0;
                s->predU[jsl][wip][1] = p1;
                s->predU[jsl][wip][2] = p2;
                s->predU[jsl][wip][3] = p3;
            }
        }
        // slice barrier: hbuf slice jsl complete for both warps
        asm volatile("bar.sync %0, 64;" :: "r"(2 + jsl) : "memory");

        // hk partial over k in slice jsl -> predH[jsl][b][uh]
        {
            ull a0 = 0, a1 = 0, a2 = 0, a3 = 0;
            const int k0 = jsl * 64;
#pragma unroll
            for (int kk = 0; kk < 64; kk += 4) {
                const int k = k0 + kk;
                ulonglong2 w  = *reinterpret_cast<const ulonglong2*>(&s->HKs2[(k >> 2) * 256 + uh * 4]);
                ulonglong2 h0 = *reinterpret_cast<const ulonglong2*>(&s->hbuf[0][k]);
                ulonglong2 h1 = *reinterpret_cast<const ulonglong2*>(&s->hbuf[1][k]);
                ulonglong2 h2 = *reinterpret_cast<const ulonglong2*>(&s->hbuf[2][k]);
                ulonglong2 h3 = *reinterpret_cast<const ulonglong2*>(&s->hbuf[3][k]);
                ffma2(a0, h0.x, w.x); ffma2(a0, h0.y, w.y);
                ffma2(a1, h1.x, w.x); ffma2(a1, h1.y, w.y);
                ffma2(a2, h2.x, w.x); ffma2(a2, h2.y, w.y);
                ffma2(a3, h3.x, w.x); ffma2(a3, h3.y, w.y);
            }
            s->predH[jsl][0][uh] = hsum2(a0);
            s->predH[jsl][1][uh] = hsum2(a1);
            s->predH[jsl][2][uh] = hsum2(a2);
            s->predH[jsl][3][uh] = hsum2(a3);
        }
        __syncthreads();   // C: all partials + mme visible

        // ======== final: u, h_t, store, flag, m_t (128 threads) ========
        if (tid < 128) {
            const int b = tid >> 5, ui = tid & 31;
            const int u0 = 2 * ui;
            float usum = xv + s->mme[b];
#pragma unroll
            for (int j = 0; j < 8; j++)
                usum += s->predU[j][0][b] + s->predU[j][1][b];
            float p0 = prex.x + usum * s->bmkl[u0];
            float p1 = prex.y + usum * s->bmkl[u0 + 1];
#pragma unroll
            for (int j = 0; j < 8; j++) {
                p0 += s->predH[j][b][u0]     + s->predQ[b][j][u0];
                p1 += s->predH[j][b][u0 + 1] + s->predQ[b][j][u0 + 1];
            }
            *reinterpret_cast<float2*>(
                &out[(size_t)((4 * g + b) * SEQ + t) * UNITS + us + u0]) =
                make_float2(tanhf(p0), tanhf(p1));
            asm volatile("bar.sync 15, 128;" ::: "memory");
            if (tid == 0)
                asm volatile("st.release.gpu.global.s32 [%0], %1;"
                             :: "l"(myflag), "r"(t + 1) : "memory");
            // m_t (local, off the inter-CTA path)
#pragma unroll
            for (int q = 0; q < 4; q++) {
                const int o = ui + 32 * q;
                float v = usum * s->bt[o];
#pragma unroll
                for (int ks = 0; ks < 4; ks++) v += s->predM[ks][b][o];
                s->mbuf[b][o] = v;
            }
        }
        __syncthreads();   // E: m_t + buffer reuse safe for next step
    }
}

// ---------------------------------------------------------------------------
extern "C" void kernel_launch(void* const* d_in, const int* in_sizes, int n_in,
                              void* d_out, int out_size) {
    const float* x  = (const float*)d_in[0];   // [64,1024,512]
    const float* ie = (const float*)d_in[1];   // [512,1]
    const float* he = (const float*)d_in[2];   // [512,1]
    const float* me = (const float*)d_in[3];   // [128,1]
    const float* IK = (const float*)d_in[4];   // [512,512]
    const float* HK = (const float*)d_in[5];   // [512,512]
    const float* MK = (const float*)d_in[6];   // [128,512]
    const float* AT = (const float*)d_in[7];   // [128,128]
    const float* BT = (const float*)d_in[8];   // [1,128]
    float* out = (float*)d_out;                // [64,1024,512]

    cudaFuncSetAttribute(recur_kernel,
                         cudaFuncAttributeMaxDynamicSharedMemorySize,
                         (int)sizeof(Smem));

    xe_kernel<<<(BATCH * SEQ) / 8, 256>>>(x, ie);
    prep_kernel<<<ORDER + 1, 512>>>(AT, BT, MK);
    gemm_kernel<<<dim3((BATCH * SEQ) / 128, UNITS / 128), 256>>>(x, IK, out);
    recur_kernel<<<dim3(8, 16), 512, sizeof(Smem)>>>(he, me, HK, MK, AT, BT, out);
}

// round 17
// speedup vs baseline: 1.7483x; 1.7483x over previous
#include <cuda_runtime.h>

#define SEQ    1024
#define BATCH  64
#define UNITS  512
#define ORDER  128
#define INDIM  512

typedef unsigned long long ull;

// scratch (device globals: no allocation allowed)
__device__ float g_xe[BATCH * SEQ];
__device__ int   g_flag[16 * 8 * 32];     // [g][slice], 128B-strided monotonic flags
__device__ float g_M2[ORDER * UNITS];     // (I+AT) @ MK, fp64-accumulated
__device__ float g_bmk[UNITS];            // BT @ MK

// ---------------------------------------------------------------------------
// f32x2 helpers
// ---------------------------------------------------------------------------
__device__ __forceinline__ void ffma2(ull& d, ull a, ull b) {
    asm("fma.rn.f32x2 %0, %1, %2, %0;" : "+l"(d) : "l"(a), "l"(b));
}
__device__ __forceinline__ ull pack2(float lo, float hi) {
    ull r;
    asm("mov.b64 %0, {%1, %2};" : "=l"(r) : "f"(lo), "f"(hi));
    return r;
}
__device__ __forceinline__ float hsum2(ull v) {
    float lo, hi;
    asm("mov.b64 {%0, %1}, %2;" : "=f"(lo), "=f"(hi) : "l"(v));
    return lo + hi;
}

// ---------------------------------------------------------------------------
// Kernel 0: M2 = (I+AT)@MK, bmk = BT@MK (fp64 accumulation).
// ---------------------------------------------------------------------------
__global__ void __launch_bounds__(512) prep_kernel(const float* __restrict__ AT,
                                                   const float* __restrict__ BT,
                                                   const float* __restrict__ MK) {
    __shared__ float row[ORDER];
    const int i = blockIdx.x;
    const int j = threadIdx.x;
    if (i < ORDER) {
        if (j < ORDER) row[j] = AT[i * ORDER + j] + (j == i ? 1.f : 0.f);
        __syncthreads();
        double acc = 0.0;
#pragma unroll 8
        for (int k = 0; k < ORDER; k++)
            acc += (double)row[k] * (double)MK[k * UNITS + j];
        g_M2[i * UNITS + j] = (float)acc;
    } else {
        double acc = 0.0;
#pragma unroll 8
        for (int k = 0; k < ORDER; k++)
            acc += (double)BT[k] * (double)MK[k * UNITS + j];
        g_bmk[j] = (float)acc;
    }
}

// ---------------------------------------------------------------------------
// Kernel 1: xe = x @ input_encoders; reset the 128 slice flags.
// ---------------------------------------------------------------------------
__global__ void __launch_bounds__(256) xe_kernel(const float* __restrict__ x,
                                                 const float* __restrict__ ie) {
    if (blockIdx.x == 0 && threadIdx.x < 128) g_flag[threadIdx.x * 32] = 0;
    const int warp = threadIdx.x >> 5;
    const int lane = threadIdx.x & 31;
    const int row  = blockIdx.x * 8 + warp;
    const float* xr = x + (size_t)row * INDIM;
    float s = 0.f;
#pragma unroll
    for (int k = lane; k < INDIM; k += 32) s += xr[k] * ie[k];
#pragma unroll
    for (int o = 16; o > 0; o >>= 1) s += __shfl_down_sync(0xffffffffu, s, o);
    if (lane == 0) g_xe[row] = s;
}

// ---------------------------------------------------------------------------
// Kernel 2: prex = X @ input_kernel (FFMA2 GEMM, proven R5..R15), into d_out.
// ---------------------------------------------------------------------------
__global__ void __launch_bounds__(256, 2) gemm_kernel(const float* __restrict__ A,
                                                      const float* __restrict__ B,
                                                      float* __restrict__ C) {
    __shared__ float As[16][132];
    __shared__ float Bs[16][128];
    const int m0  = blockIdx.x * 128;
    const int n0  = blockIdx.y * 128;
    const int tid = threadIdx.x;
    const int tx  = tid & 15;
    const int ty  = tid >> 4;

    ull acc[8][4];
#pragma unroll
    for (int i = 0; i < 8; i++)
#pragma unroll
        for (int j = 0; j < 4; j++) acc[i][j] = 0ull;

    for (int k0 = 0; k0 < 512; k0 += 16) {
#pragma unroll
        for (int i = 0; i < 2; i++) {
            int idx = tid + i * 256;
            int row = idx >> 2;
            int c4  = (idx & 3) << 2;
            float4 v = *reinterpret_cast<const float4*>(&A[(size_t)(m0 + row) * 512 + k0 + c4]);
            As[c4 + 0][row] = v.x; As[c4 + 1][row] = v.y;
            As[c4 + 2][row] = v.z; As[c4 + 3][row] = v.w;
        }
#pragma unroll
        for (int i = 0; i < 2; i++) {
            int idx = tid + i * 256;
            int row = idx >> 5;
            int c4  = (idx & 31) << 2;
            *reinterpret_cast<float4*>(&Bs[row][c4]) =
                *reinterpret_cast<const float4*>(&B[(size_t)(k0 + row) * 512 + n0 + c4]);
        }
        __syncthreads();
#pragma unroll
        for (int k = 0; k < 16; k++) {
            ulonglong2 b01 = *reinterpret_cast<const ulonglong2*>(&Bs[k][tx * 8]);
            ulonglong2 b23 = *reinterpret_cast<const ulonglong2*>(&Bs[k][tx * 8 + 4]);
            float4 ra0 = *reinterpret_cast<const float4*>(&As[k][ty * 8]);
            float4 ra1 = *reinterpret_cast<const float4*>(&As[k][ty * 8 + 4]);
            float rm[8] = {ra0.x, ra0.y, ra0.z, ra0.w, ra1.x, ra1.y, ra1.z, ra1.w};
#pragma unroll
            for (int i = 0; i < 8; i++) {
                ull rp = pack2(rm[i], rm[i]);
                ffma2(acc[i][0], rp, b01.x);
                ffma2(acc[i][1], rp, b01.y);
                ffma2(acc[i][2], rp, b23.x);
                ffma2(acc[i][3], rp, b23.y);
            }
        }
        __syncthreads();
    }
#pragma unroll
    for (int i = 0; i < 8; i++) {
        size_t base = (size_t)(m0 + ty * 8 + i) * 512 + n0 + tx * 8;
        ulonglong2 o0; o0.x = acc[i][0]; o0.y = acc[i][1];
        ulonglong2 o1; o1.x = acc[i][2]; o1.y = acc[i][3];
        *reinterpret_cast<ulonglong2*>(&C[base])     = o0;
        *reinterpret_cast<ulonglong2*>(&C[base + 4]) = o1;
    }
}

// ---------------------------------------------------------------------------
// Kernel 3: recurrence, dataflow exchange, crossbar-optimized.
//   h_t = tanh(prex + h_{t-1}@HK + m_{t-1}@M2 + u_t*bmk)
//   m_t = m_{t-1}@(I+AT) + u_t*BT
// R16 changes vs R15:
//  - predM thread remap (o3=tid&127, ks3=tid>>7): m-loads are warp-uniform
//    broadcasts (1 wf) instead of 4-way bank-conflicted (4 wf).
//  - mq (m@M2) partial kept in the hk accumulator REGISTERS across the
//    exchange: predQ smem array eliminated (no store+reload round trip).
// ---------------------------------------------------------------------------
struct Smem {
    float HKs2[UNITS * 64];   // 131072 B: [(k>>2)*256 + u*4 + (k&3)]
    float M2s2[ORDER * 64];   //  32768 B: same packing
    float hbuf[4][512];       //   8192 B: slice j region owned by warp-group j
    float mbuf[4][128];       //   2048 B: m_{t-1}
    float predH[8][4][64];    //   8192 B: (hk+mq) partials [j][b][u]
    float predM[4][4][128];   //   8192 B: m@(I+AT)         [ks3][b][o3]
    float predU[8][2][4];     //    256 B: h·he partials    [j][warp][b]
    float he[512];
    float me[128];
    float bt[128];
    float bmkl[64];
    float mme[4];
};

__global__ void __launch_bounds__(512, 1)
recur_kernel(const float* __restrict__ he, const float* __restrict__ me,
             const float* __restrict__ HK, const float* __restrict__ MK,
             const float* __restrict__ AT, const float* __restrict__ BT,
             float* __restrict__ out) {
    extern __shared__ __align__(16) unsigned char smem_raw[];
    Smem* s = reinterpret_cast<Smem*>(smem_raw);

    const int tid = threadIdx.x;
    const int sl  = blockIdx.x;      // produced slice 0..7
    const int g   = blockIdx.y;      // batch group 0..15
    const int us  = sl * 64;

    // ---- stationary weights ----
    for (int i = tid; i < UNITS * 64; i += 512) {
        int k = i >> 6, u = i & 63;
        s->HKs2[(k >> 2) * 256 + u * 4 + (k & 3)] = HK[k * 512 + us + u];
    }
    for (int i = tid; i < ORDER * 64; i += 512) {
        int k = i >> 6, u = i & 63;
        s->M2s2[(k >> 2) * 256 + u * 4 + (k & 3)] = g_M2[k * 512 + us + u];
    }
    s->he[tid] = he[tid];
    if (tid < 128) { s->me[tid] = me[tid]; s->bt[tid] = BT[tid]; }
    if (tid < 64)  s->bmkl[tid] = g_bmk[us + tid];
    if (tid < 128) (&s->mbuf[0][0])[tid * 4 + 0] = 0.f,
                   (&s->mbuf[0][0])[tid * 4 + 1] = 0.f,
                   (&s->mbuf[0][0])[tid * 4 + 2] = 0.f,
                   (&s->mbuf[0][0])[tid * 4 + 3] = 0.f;

    // (I+AT) in registers, REMAPPED: o3 = tid&127 (lane-consecutive),
    // ks3 = tid>>7. Within a warp all lanes share ks3 -> m loads broadcast.
    const int o3 = tid & 127, ks3 = tid >> 7, kb3 = ks3 * 32;
    ull am2[16];
#pragma unroll
    for (int j = 0; j < 16; j++) {
        int k = kb3 + 2 * j;
        float a0 = AT[k * 128 + o3]       + (k == o3       ? 1.f : 0.f);
        float a1 = AT[(k + 1) * 128 + o3] + ((k + 1) == o3 ? 1.f : 0.f);
        am2[j] = pack2(a0, a1);
    }
    __syncthreads();

    const int uh  = tid & 63, ksh = tid >> 6;     // slice-group layout
    const int jsl = ksh;                           // consumed slice id
    const int wip = (tid >> 5) & 1;                // warp within pair
    volatile int* myflag = &g_flag[(g * 8 + sl) * 32];
    const int* cflag = &g_flag[(g * 8 + jsl) * 32];

    for (int t = 0; t < SEQ; ++t) {
        // ======== phase A: purely local (m_{t-1}) ========
        float2 prex = make_float2(0.f, 0.f);
        float  xv = 0.f;
        if (tid < 128) {
            int b = tid >> 5, ui = tid & 31;
            prex = __ldg(reinterpret_cast<const float2*>(
                &out[(size_t)((4 * g + b) * SEQ + t) * UNITS + us + 2 * ui]));
            xv = __ldg(&g_xe[(4 * g + b) * SEQ + t]);
            // mme partial: m·me
            float pm = 0.f;
#pragma unroll
            for (int q = 0; q < 4; q++)
                pm += s->mbuf[b][ui + 32 * q] * s->me[ui + 32 * q];
#pragma unroll
            for (int o = 16; o > 0; o >>= 1)
                pm += __shfl_down_sync(0xffffffffu, pm, o);
            if (ui == 0) s->mme[b] = pm;
        }

        // mq partial: m_{t-1} @ M2 slice -> kept in REGISTERS a0..a3
        // (same (ksh,uh) layout as hk; hk accumulates on top after exchange)
        ull a0 = 0, a1 = 0, a2 = 0, a3 = 0;
        {
            const int k0 = ksh * 16;
#pragma unroll
            for (int kk = 0; kk < 16; kk += 4) {
                const int k = k0 + kk;
                ulonglong2 w  = *reinterpret_cast<const ulonglong2*>(&s->M2s2[(k >> 2) * 256 + uh * 4]);
                ulonglong2 m0 = *reinterpret_cast<const ulonglong2*>(&s->mbuf[0][k]);
                ulonglong2 m1 = *reinterpret_cast<const ulonglong2*>(&s->mbuf[1][k]);
                ulonglong2 m2 = *reinterpret_cast<const ulonglong2*>(&s->mbuf[2][k]);
                ulonglong2 m3 = *reinterpret_cast<const ulonglong2*>(&s->mbuf[3][k]);
                ffma2(a0, m0.x, w.x); ffma2(a0, m0.y, w.y);
                ffma2(a1, m1.x, w.x); ffma2(a1, m1.y, w.y);
                ffma2(a2, m2.x, w.x); ffma2(a2, m2.y, w.y);
                ffma2(a3, m3.x, w.x); ffma2(a3, m3.y, w.y);
            }
        }

        // predM partial: m_{t-1} @ (I+AT) -> predM[ks3][b][o3]
        // (broadcast m loads: all lanes in a warp share ks3 => same address)
        {
            ull c0 = 0, c1 = 0, c2 = 0, c3 = 0;
#pragma unroll
            for (int j = 0; j < 16; j += 2) {
                const int k = kb3 + 2 * j;
                ulonglong2 m0 = *reinterpret_cast<const ulonglong2*>(&s->mbuf[0][k]);
                ulonglong2 m1 = *reinterpret_cast<const ulonglong2*>(&s->mbuf[1][k]);
                ulonglong2 m2 = *reinterpret_cast<const ulonglong2*>(&s->mbuf[2][k]);
                ulonglong2 m3 = *reinterpret_cast<const ulonglong2*>(&s->mbuf[3][k]);
                ffma2(c0, m0.x, am2[j]); ffma2(c0, m0.y, am2[j + 1]);
                ffma2(c1, m1.x, am2[j]); ffma2(c1, m1.y, am2[j + 1]);
                ffma2(c2, m2.x, am2[j]); ffma2(c2, m2.y, am2[j + 1]);
                ffma2(c3, m3.x, am2[j]); ffma2(c3, m3.y, am2[j + 1]);
            }
            s->predM[ks3][0][o3] = hsum2(c0);
            s->predM[ks3][1][o3] = hsum2(c1);
            s->predM[ks3][2][o3] = hsum2(c2);
            s->predM[ks3][3][o3] = hsum2(c3);
        }

        // ======== phase B: per-slice consume (warp-group jsl) ========
        float hv0 = 0.f, hv1 = 0.f, hv2 = 0.f, hv3 = 0.f;
        if (t > 0) {
            if ((tid & 63) == 0) {
                int f;
                while (true) {
                    asm volatile("ld.acquire.gpu.global.s32 %0, [%1];"
                                 : "=r"(f) : "l"(cflag) : "memory");
                    if (f >= t) break;
                    __nanosleep(32);
                }
            }
            asm volatile("bar.sync %0, 64;" :: "r"(2 + jsl) : "memory");
            const size_t tb = (size_t)(4 * g) * SEQ + (t - 1);
            hv0 = __ldcg(&out[(tb           ) * UNITS + jsl * 64 + uh]);
            hv1 = __ldcg(&out[(tb +     SEQ ) * UNITS + jsl * 64 + uh]);
            hv2 = __ldcg(&out[(tb + 2 * SEQ ) * UNITS + jsl * 64 + uh]);
            hv3 = __ldcg(&out[(tb + 3 * SEQ ) * UNITS + jsl * 64 + uh]);
        }
        s->hbuf[0][jsl * 64 + uh] = hv0;
        s->hbuf[1][jsl * 64 + uh] = hv1;
        s->hbuf[2][jsl * 64 + uh] = hv2;
        s->hbuf[3][jsl * 64 + uh] = hv3;

        // u-dot partial from own registers
        {
            const float hek = s->he[jsl * 64 + uh];
            float p0 = hv0 * hek, p1 = hv1 * hek, p2 = hv2 * hek, p3 = hv3 * hek;
#pragma unroll
            for (int o = 16; o > 0; o >>= 1) {
                p0 += __shfl_down_sync(0xffffffffu, p0, o);
                p1 += __shfl_down_sync(0xffffffffu, p1, o);
                p2 += __shfl_down_sync(0xffffffffu, p2, o);
                p3 += __shfl_down_sync(0xffffffffu, p3, o);
            }
            if ((tid & 31) == 0) {
                s->predU[jsl][wip][0] = p0;
                s->predU[jsl][wip][1] = p1;
                s->predU[jsl][wip][2] = p2;
                s->predU[jsl][wip][3] = p3;
            }
        }
        // slice barrier: hbuf slice jsl complete for both warps
        asm volatile("bar.sync %0, 64;" :: "r"(2 + jsl) : "memory");

        // hk partial over k in slice jsl, ACCUMULATED onto mq registers
        {
            const int k0 = jsl * 64;
#pragma unroll
            for (int kk = 0; kk < 64; kk += 4) {
                const int k = k0 + kk;
                ulonglong2 w  = *reinterpret_cast<const ulonglong2*>(&s->HKs2[(k >> 2) * 256 + uh * 4]);
                ulonglong2 h0 = *reinterpret_cast<const ulonglong2*>(&s->hbuf[0][k]);
                ulonglong2 h1 = *reinterpret_cast<const ulonglong2*>(&s->hbuf[1][k]);
                ulonglong2 h2 = *reinterpret_cast<const ulonglong2*>(&s->hbuf[2][k]);
                ulonglong2 h3 = *reinterpret_cast<const ulonglong2*>(&s->hbuf[3][k]);
                ffma2(a0, h0.x, w.x); ffma2(a0, h0.y, w.y);
                ffma2(a1, h1.x, w.x); ffma2(a1, h1.y, w.y);
                ffma2(a2, h2.x, w.x); ffma2(a2, h2.y, w.y);
                ffma2(a3, h3.x, w.x); ffma2(a3, h3.y, w.y);
            }
            s->predH[jsl][0][uh] = hsum2(a0);
            s->predH[jsl][1][uh] = hsum2(a1);
            s->predH[jsl][2][uh] = hsum2(a2);
            s->predH[jsl][3][uh] = hsum2(a3);
        }
        __syncthreads();   // C: all partials + mme visible

        // ======== final: u, h_t, store, flag, m_t (128 threads) ========
        if (tid < 128) {
            const int b = tid >> 5, ui = tid & 31;
            const int u0 = 2 * ui;
            float usum = xv + s->mme[b];
#pragma unroll
            for (int j = 0; j < 8; j++)
                usum += s->predU[j][0][b] + s->predU[j][1][b];
            float p0 = prex.x + usum * s->bmkl[u0];
            float p1 = prex.y + usum * s->bmkl[u0 + 1];
#pragma unroll
            for (int j = 0; j < 8; j++) {
                p0 += s->predH[j][b][u0];
                p1 += s->predH[j][b][u0 + 1];
            }
            *reinterpret_cast<float2*>(
                &out[(size_t)((4 * g + b) * SEQ + t) * UNITS + us + u0]) =
                make_float2(tanhf(p0), tanhf(p1));
            asm volatile("bar.sync 15, 128;" ::: "memory");
            if (tid == 0)
                asm volatile("st.release.gpu.global.s32 [%0], %1;"
                             :: "l"(myflag), "r"(t + 1) : "memory");
            // m_t (local, off the inter-CTA path)
#pragma unroll
            for (int q = 0; q < 4; q++) {
                const int o = ui + 32 * q;
                float v = usum * s->bt[o];
#pragma unroll
                for (int ks = 0; ks < 4; ks++) v += s->predM[ks][b][o];
                s->mbuf[b][o] = v;
            }
        }
        __syncthreads();   // E: m_t + buffer reuse safe for next step
    }
}

// ---------------------------------------------------------------------------
extern "C" void kernel_launch(void* const* d_in, const int* in_sizes, int n_in,
                              void* d_out, int out_size) {
    const float* x  = (const float*)d_in[0];   // [64,1024,512]
    const float* ie = (const float*)d_in[1];   // [512,1]
    const float* he = (const float*)d_in[2];   // [512,1]
    const float* me = (const float*)d_in[3];   // [128,1]
    const float* IK = (const float*)d_in[4];   // [512,512]
    const float* HK = (const float*)d_in[5];   // [512,512]
    const float* MK = (const float*)d_in[6];   // [128,512]
    const float* AT = (const float*)d_in[7];   // [128,128]
    const float* BT = (const float*)d_in[8];   // [1,128]
    float* out = (float*)d_out;                // [64,1024,512]

    cudaFuncSetAttribute(recur_kernel,
                         cudaFuncAttributeMaxDynamicSharedMemorySize,
                         (int)sizeof(Smem));

    xe_kernel<<<(BATCH * SEQ) / 8, 256>>>(x, ie);
    prep_kernel<<<ORDER + 1, 512>>>(AT, BT, MK);
    gemm_kernel<<<dim3((BATCH * SEQ) / 128, UNITS / 128), 256>>>(x, IK, out);
    recur_kernel<<<dim3(8, 16), 512, sizeof(Smem)>>>(he, me, HK, MK, AT, BT, out);
}